// round 4
// baseline (speedup 1.0000x reference)
#include <cuda_runtime.h>

#define NN 50000
#define NE 600000
#define DIM 128

// ---- device-global scratch (no runtime allocation allowed) ----
__device__ int   g_mode;          // 1 = edge_index is int64, 0 = int32
__device__ int   g_deg[NN];
__device__ int   g_off[NN + 1];
__device__ int   g_cur[NN];
__device__ float g_inv[NN];
__device__ int   g_csr[NE];
__device__ float g_agg[(size_t)NN * DIM];
__device__ float g_h[(size_t)NN * DIM];

// ---------------- edge-index dtype probe + decode ----------------

__global__ void k_probe(const void* __restrict__ ei, int n, int e) {
    if (threadIdx.x != 0 || blockIdx.x != 0) return;
    const long long* p = (const long long*)ei;
    int cnt = min(16, e);
    int ok = 1;
    for (int i = 0; i < cnt; i++) {
        long long v = p[i];                // bytes < 128: in-bounds either way
        if (v < 0 || v >= (long long)n) { ok = 0; break; }
    }
    g_mode = ok;                           // 1 => int64, 0 => int32
}

__device__ __forceinline__ int edge_at(const void* __restrict__ ei, int e,
                                       int which, int i, int mode) {
    if (mode) return (int)((const long long*)ei)[(size_t)which * e + i];
    return ((const int*)ei)[(size_t)which * e + i];
}

// ---------------- CSR build ----------------

__global__ void k_zero_deg(int n) {
    int i = blockIdx.x * blockDim.x + threadIdx.x;
    if (i < n) g_deg[i] = 0;
}

__global__ void k_hist(const void* __restrict__ ei, int e) {
    int i = blockIdx.x * blockDim.x + threadIdx.x;
    if (i < e) {
        int mode = g_mode;
        int d = edge_at(ei, e, 1, i, mode);
        atomicAdd(&g_deg[d], 1);
    }
}

// single-block exclusive scan over degrees; also writes cursor + 1/max(deg,1)
__global__ void k_scan(int n, int e) {
    __shared__ int sm[1024];
    int t = threadIdx.x;
    int chunk = (n + 1023) >> 10;
    int beg = t * chunk;
    int end = min(beg + chunk, n);
    int s = 0;
    for (int i = beg; i < end; i++) s += g_deg[i];
    sm[t] = s;
    __syncthreads();
    for (int d = 1; d < 1024; d <<= 1) {
        int v = (t >= d) ? sm[t - d] : 0;
        __syncthreads();
        sm[t] += v;
        __syncthreads();
    }
    int run = (t == 0) ? 0 : sm[t - 1];
    for (int i = beg; i < end; i++) {
        int dg = g_deg[i];
        g_off[i] = run;
        g_cur[i] = run;
        g_inv[i] = 1.0f / (float)max(dg, 1);
        run += dg;
    }
    if (t == 1023) g_off[n] = e;
}

__global__ void k_fill(const void* __restrict__ ei, int e) {
    int i = blockIdx.x * blockDim.x + threadIdx.x;
    if (i < e) {
        int mode = g_mode;
        int d = edge_at(ei, e, 1, i, mode);
        int s = edge_at(ei, e, 0, i, mode);
        int p = atomicAdd(&g_cur[d], 1);
        g_csr[p] = s;
    }
}

// ---------------- mean aggregation: one warp per node ----------------
// FROM_H selects the feature source (input x vs hidden g_h); writes g_agg.

template <bool FROM_H>
__global__ void k_agg(const float* __restrict__ xin, int n) {
    int w = (blockIdx.x * blockDim.x + threadIdx.x) >> 5;
    int lane = threadIdx.x & 31;
    if (w >= n) return;
    const float* feat = FROM_H ? (const float*)g_h : xin;
    int beg = g_off[w];
    int end = g_off[w + 1];
    const float4* fp = (const float4*)feat;
    float4 s = make_float4(0.f, 0.f, 0.f, 0.f);
#pragma unroll 4
    for (int e = beg; e < end; ++e) {
        int j = __ldg(&g_csr[e]);
        float4 v = __ldg(&fp[(size_t)j * 32 + lane]);
        s.x += v.x; s.y += v.y; s.z += v.z; s.w += v.w;
    }
    float iv = g_inv[w];
    ((float4*)g_agg)[(size_t)w * 32 + lane] =
        make_float4(s.x * iv, s.y * iv, s.z * iv, s.w * iv);
}

// ---------------- fused transform: out = g_agg@Wl + X@Wr + b (optional relu) --------
// Block: 256 threads, 64 rows, K-tiled in chunks of 32 -> 48KB static smem.
// Thread (warp w, lane colg): 4 output cols (4*colg..+3) x 8 rows (w*8..+7).
// X_FROM_H: X = g_h (else external x). OUT_TO_H: write g_h (else external out).

#define XF_ROWS 64
#define KCH 32

template <bool X_FROM_H, bool OUT_TO_H, bool RELU>
__global__ void __launch_bounds__(256)
k_xform(const float* __restrict__ Xin,
        const float* __restrict__ Wl, const float* __restrict__ Wr,
        const float* __restrict__ bias, float* __restrict__ outp, int n) {
    __shared__ float Wl_t[KCH * 128];       // 16 KB
    __shared__ float Wr_t[KCH * 128];       // 16 KB
    __shared__ float A_t[XF_ROWS * KCH];    // 8 KB
    __shared__ float X_t[XF_ROWS * KCH];    // 8 KB

    const float* A = g_agg;
    const float* X = X_FROM_H ? (const float*)g_h : Xin;
    float* out = OUT_TO_H ? (float*)g_h : outp;

    int tx = threadIdx.x;
    int colg = tx & 31;
    int wrp = tx >> 5;  // warp 0..7 owns rows wrp*8 .. wrp*8+7
    int row0 = blockIdx.x * XF_ROWS;

    float4 acc[8];
#pragma unroll
    for (int r = 0; r < 8; r++) acc[r] = make_float4(0.f, 0.f, 0.f, 0.f);

    for (int kc = 0; kc < 128 / KCH; kc++) {
        __syncthreads();
        // weights chunk: rows kc*32..+31 of [128][128]; 1024 float4 per matrix
#pragma unroll
        for (int i = 0; i < 4; i++) {
            int idx = tx + i * 256;          // float4 index 0..1023
            int r = idx >> 5;
            int c4 = idx & 31;
            ((float4*)Wl_t)[idx] = __ldg(&((const float4*)Wl)[(kc * KCH + r) * 32 + c4]);
            ((float4*)Wr_t)[idx] = __ldg(&((const float4*)Wr)[(kc * KCH + r) * 32 + c4]);
        }
        // A/X chunk: 64 rows x 32 cols = 512 float4 each
#pragma unroll
        for (int i = 0; i < 2; i++) {
            int idx = tx + i * 256;          // float4 index 0..511
            int r = idx >> 3;
            int c4 = idx & 7;
            int row = row0 + r;
            float4 av = make_float4(0.f, 0.f, 0.f, 0.f);
            float4 xv = av;
            if (row < n) {
                av = __ldg(&((const float4*)A)[(size_t)row * 32 + kc * 8 + c4]);
                xv = __ldg(&((const float4*)X)[(size_t)row * 32 + kc * 8 + c4]);
            }
            ((float4*)A_t)[idx] = av;
            ((float4*)X_t)[idx] = xv;
        }
        __syncthreads();

#pragma unroll 4
        for (int k = 0; k < KCH; k++) {
            float4 wl = ((float4*)Wl_t)[k * 32 + colg];
            float4 wrv = ((float4*)Wr_t)[k * 32 + colg];
#pragma unroll
            for (int r = 0; r < 8; r++) {
                float a = A_t[(wrp * 8 + r) * KCH + k];   // warp-uniform broadcast
                float xx = X_t[(wrp * 8 + r) * KCH + k];  // warp-uniform broadcast
                acc[r].x = fmaf(a, wl.x, acc[r].x); acc[r].x = fmaf(xx, wrv.x, acc[r].x);
                acc[r].y = fmaf(a, wl.y, acc[r].y); acc[r].y = fmaf(xx, wrv.y, acc[r].y);
                acc[r].z = fmaf(a, wl.z, acc[r].z); acc[r].z = fmaf(xx, wrv.z, acc[r].z);
                acc[r].w = fmaf(a, wl.w, acc[r].w); acc[r].w = fmaf(xx, wrv.w, acc[r].w);
            }
        }
    }

    float4 bv = __ldg(&((const float4*)bias)[colg]);
#pragma unroll
    for (int r = 0; r < 8; r++) {
        int row = row0 + wrp * 8 + r;
        if (row < n) {
            float4 o;
            o.x = acc[r].x + bv.x;
            o.y = acc[r].y + bv.y;
            o.z = acc[r].z + bv.z;
            o.w = acc[r].w + bv.w;
            if (RELU) {
                o.x = fmaxf(o.x, 0.f);
                o.y = fmaxf(o.y, 0.f);
                o.z = fmaxf(o.z, 0.f);
                o.w = fmaxf(o.w, 0.f);
            }
            ((float4*)out)[(size_t)row * 32 + colg] = o;
        }
    }
}

// ---------------- launch: kernel launches ONLY, no other CUDA API ----------------

extern "C" void kernel_launch(void* const* d_in, const int* in_sizes, int n_in,
                              void* d_out, int out_size) {
    const float* x   = (const float*)d_in[0];
    const void*  ei  = d_in[1];
    const float* Wl1 = (const float*)d_in[2];
    const float* Wr1 = (const float*)d_in[3];
    const float* b1  = (const float*)d_in[4];
    const float* Wl2 = (const float*)d_in[5];
    const float* Wr2 = (const float*)d_in[6];
    const float* b2  = (const float*)d_in[7];
    float*       out = (float*)d_out;

    int n = in_sizes[0] / DIM;
    int e = in_sizes[1] / 2;

    // detect edge_index dtype (int32 vs int64), then build CSR
    k_probe<<<1, 32>>>(ei, n, e);
    k_zero_deg<<<(n + 255) / 256, 256>>>(n);
    k_hist<<<(e + 255) / 256, 256>>>(ei, e);
    k_scan<<<1, 1024>>>(n, e);
    k_fill<<<(e + 255) / 256, 256>>>(ei, e);

    int agg_blocks = (n * 32 + 255) / 256;
    int xf_blocks = (n + XF_ROWS - 1) / XF_ROWS;

    // layer 1: agg(x) -> g_agg ; g_h = relu(g_agg@Wl1 + x@Wr1 + b1)
    k_agg<false><<<agg_blocks, 256>>>(x, n);
    k_xform<false, true, true><<<xf_blocks, 256>>>(x, Wl1, Wr1, b1, out, n);

    // layer 2: agg(g_h) -> g_agg ; out = g_agg@Wl2 + g_h@Wr2 + b2
    k_agg<true><<<agg_blocks, 256>>>(x, n);
    k_xform<true, false, false><<<xf_blocks, 256>>>(x, Wl2, Wr2, b2, out, n);
}

// round 7
// speedup vs baseline: 1.3926x; 1.3926x over previous
#include <cuda_runtime.h>

#define NN 50000
#define NE 600000
#define DIM 128

#define SCAN_B 1024
#define NBLK ((NN + SCAN_B - 1) / SCAN_B)   // 49

// ---- device-global scratch (no runtime allocation allowed) ----
__device__ int   g_mode;          // 1 = edge_index is int64, 0 = int32
__device__ int   g_deg[NN];
__device__ int   g_off[NN + 1];
__device__ int   g_cur[NN];
__device__ float g_inv[NN];
__device__ int   g_blk[NBLK];
__device__ int   g_csr[NE];
__device__ float g_agg[(size_t)NN * DIM];
__device__ float g_h[(size_t)NN * DIM];

// ---------------- edge-index dtype probe + decode ----------------

__global__ void k_probe(const void* __restrict__ ei, int n, int e) {
    if (threadIdx.x != 0 || blockIdx.x != 0) return;
    const long long* p = (const long long*)ei;
    int cnt = min(16, e);
    int ok = 1;
    for (int i = 0; i < cnt; i++) {
        long long v = p[i];                // bytes < 128: in-bounds either way
        if (v < 0 || v >= (long long)n) { ok = 0; break; }
    }
    g_mode = ok;                           // 1 => int64, 0 => int32
}

__device__ __forceinline__ int edge_at(const void* __restrict__ ei, int e,
                                       int which, int i, int mode) {
    if (mode) return (int)((const long long*)ei)[(size_t)which * e + i];
    return ((const int*)ei)[(size_t)which * e + i];
}

// ---------------- CSR build ----------------

__global__ void k_zero_deg(int n) {
    int i = blockIdx.x * blockDim.x + threadIdx.x;
    if (i < n) g_deg[i] = 0;
}

__global__ void k_hist(const void* __restrict__ ei, int e) {
    int i = blockIdx.x * blockDim.x + threadIdx.x;
    if (i < e) {
        int mode = g_mode;
        int d = edge_at(ei, e, 1, i, mode);
        atomicAdd(&g_deg[d], 1);
    }
}

// ---- multi-block exclusive scan over degrees (3 kernels) ----

// 1: per-block inclusive scan -> g_off (inclusive, block-local), block totals -> g_blk
__global__ void k_scan1(int n) {
    __shared__ int sm[SCAN_B];
    int t = threadIdx.x;
    int i = blockIdx.x * SCAN_B + t;
    int v = (i < n) ? g_deg[i] : 0;
    sm[t] = v;
    __syncthreads();
#pragma unroll
    for (int d = 1; d < SCAN_B; d <<= 1) {
        int u = (t >= d) ? sm[t - d] : 0;
        __syncthreads();
        sm[t] += u;
        __syncthreads();
    }
    if (i < n) g_off[i] = sm[t];           // block-local inclusive
    if (t == SCAN_B - 1) g_blk[blockIdx.x] = sm[t];
}

// 2: one small block scans block totals into exclusive bases
__global__ void k_scan2() {
    __shared__ int sm[64];
    int t = threadIdx.x;                   // 64 >= NBLK
    int v = (t < NBLK) ? g_blk[t] : 0;
    sm[t] = v;
    __syncthreads();
#pragma unroll
    for (int d = 1; d < 64; d <<= 1) {
        int u = (t >= d) ? sm[t - d] : 0;
        __syncthreads();
        sm[t] += u;
        __syncthreads();
    }
    if (t < NBLK) g_blk[t] = sm[t] - v;    // exclusive base
}

// 3: finalize exclusive offsets + cursor + 1/deg
__global__ void k_scan3(int n, int e) {
    int t = threadIdx.x;
    int i = blockIdx.x * SCAN_B + t;
    if (i < n) {
        int dg = g_deg[i];
        int excl = g_blk[blockIdx.x] + g_off[i] - dg;
        g_off[i] = excl;
        g_cur[i] = excl;
        g_inv[i] = 1.0f / (float)max(dg, 1);
    }
    if (i == 0) g_off[n] = e;
}

__global__ void k_fill(const void* __restrict__ ei, int e) {
    int i = blockIdx.x * blockDim.x + threadIdx.x;
    if (i < e) {
        int mode = g_mode;
        int d = edge_at(ei, e, 1, i, mode);
        int s = edge_at(ei, e, 0, i, mode);
        int p = atomicAdd(&g_cur[d], 1);
        g_csr[p] = s;
    }
}

// ---------------- mean aggregation: one warp per node ----------------

template <bool FROM_H>
__global__ void k_agg(const float* __restrict__ xin, int n) {
    int w = (blockIdx.x * blockDim.x + threadIdx.x) >> 5;
    int lane = threadIdx.x & 31;
    if (w >= n) return;
    const float* feat = FROM_H ? (const float*)g_h : xin;
    int beg = g_off[w];
    int end = g_off[w + 1];
    const float4* fp = (const float4*)feat;
    float4 s = make_float4(0.f, 0.f, 0.f, 0.f);
#pragma unroll 4
    for (int e = beg; e < end; ++e) {
        int j = __ldg(&g_csr[e]);
        float4 v = __ldg(&fp[(size_t)j * 32 + lane]);
        s.x += v.x; s.y += v.y; s.z += v.z; s.w += v.w;
    }
    float iv = g_inv[w];
    ((float4*)g_agg)[(size_t)w * 32 + lane] =
        make_float4(s.x * iv, s.y * iv, s.z * iv, s.w * iv);
}

// ---------------- fused transform: out = g_agg@Wl + X@Wr + b (optional relu) --------

#define XF_ROWS 64
#define KCH 32

template <bool X_FROM_H, bool OUT_TO_H, bool RELU>
__global__ void __launch_bounds__(256)
k_xform(const float* __restrict__ Xin,
        const float* __restrict__ Wl, const float* __restrict__ Wr,
        const float* __restrict__ bias, float* __restrict__ outp, int n) {
    __shared__ float Wl_t[KCH * 128];       // 16 KB
    __shared__ float Wr_t[KCH * 128];       // 16 KB
    __shared__ float A_t[XF_ROWS * KCH];    // 8 KB
    __shared__ float X_t[XF_ROWS * KCH];    // 8 KB

    const float* A = g_agg;
    const float* X = X_FROM_H ? (const float*)g_h : Xin;
    float* out = OUT_TO_H ? (float*)g_h : outp;

    int tx = threadIdx.x;
    int colg = tx & 31;
    int wrp = tx >> 5;  // warp 0..7 owns rows wrp*8 .. wrp*8+7
    int row0 = blockIdx.x * XF_ROWS;

    float4 acc[8];
#pragma unroll
    for (int r = 0; r < 8; r++) acc[r] = make_float4(0.f, 0.f, 0.f, 0.f);

    for (int kc = 0; kc < 128 / KCH; kc++) {
        __syncthreads();
#pragma unroll
        for (int i = 0; i < 4; i++) {
            int idx = tx + i * 256;          // float4 index 0..1023
            int r = idx >> 5;
            int c4 = idx & 31;
            ((float4*)Wl_t)[idx] = __ldg(&((const float4*)Wl)[(kc * KCH + r) * 32 + c4]);
            ((float4*)Wr_t)[idx] = __ldg(&((const float4*)Wr)[(kc * KCH + r) * 32 + c4]);
        }
#pragma unroll
        for (int i = 0; i < 2; i++) {
            int idx = tx + i * 256;          // float4 index 0..511
            int r = idx >> 3;
            int c4 = idx & 7;
            int row = row0 + r;
            float4 av = make_float4(0.f, 0.f, 0.f, 0.f);
            float4 xv = av;
            if (row < n) {
                av = __ldg(&((const float4*)A)[(size_t)row * 32 + kc * 8 + c4]);
                xv = __ldg(&((const float4*)X)[(size_t)row * 32 + kc * 8 + c4]);
            }
            ((float4*)A_t)[idx] = av;
            ((float4*)X_t)[idx] = xv;
        }
        __syncthreads();

#pragma unroll 4
        for (int k = 0; k < KCH; k++) {
            float4 wl = ((float4*)Wl_t)[k * 32 + colg];
            float4 wrv = ((float4*)Wr_t)[k * 32 + colg];
#pragma unroll
            for (int r = 0; r < 8; r++) {
                float a = A_t[(wrp * 8 + r) * KCH + k];
                float xx = X_t[(wrp * 8 + r) * KCH + k];
                acc[r].x = fmaf(a, wl.x, acc[r].x); acc[r].x = fmaf(xx, wrv.x, acc[r].x);
                acc[r].y = fmaf(a, wl.y, acc[r].y); acc[r].y = fmaf(xx, wrv.y, acc[r].y);
                acc[r].z = fmaf(a, wl.z, acc[r].z); acc[r].z = fmaf(xx, wrv.z, acc[r].z);
                acc[r].w = fmaf(a, wl.w, acc[r].w); acc[r].w = fmaf(xx, wrv.w, acc[r].w);
            }
        }
    }

    float4 bv = __ldg(&((const float4*)bias)[colg]);
#pragma unroll
    for (int r = 0; r < 8; r++) {
        int row = row0 + wrp * 8 + r;
        if (row < n) {
            float4 o;
            o.x = acc[r].x + bv.x;
            o.y = acc[r].y + bv.y;
            o.z = acc[r].z + bv.z;
            o.w = acc[r].w + bv.w;
            if (RELU) {
                o.x = fmaxf(o.x, 0.f);
                o.y = fmaxf(o.y, 0.f);
                o.z = fmaxf(o.z, 0.f);
                o.w = fmaxf(o.w, 0.f);
            }
            ((float4*)out)[(size_t)row * 32 + colg] = o;
        }
    }
}

// ---------------- launch: kernel launches ONLY ----------------

extern "C" void kernel_launch(void* const* d_in, const int* in_sizes, int n_in,
                              void* d_out, int out_size) {
    const float* x   = (const float*)d_in[0];
    const void*  ei  = d_in[1];
    const float* Wl1 = (const float*)d_in[2];
    const float* Wr1 = (const float*)d_in[3];
    const float* b1  = (const float*)d_in[4];
    const float* Wl2 = (const float*)d_in[5];
    const float* Wr2 = (const float*)d_in[6];
    const float* b2  = (const float*)d_in[7];
    float*       out = (float*)d_out;

    int n = in_sizes[0] / DIM;
    int e = in_sizes[1] / 2;

    int scan_blocks = (n + SCAN_B - 1) / SCAN_B;

    // detect edge_index dtype (int32 vs int64), then build CSR
    k_probe<<<1, 32>>>(ei, n, e);
    k_zero_deg<<<(n + 255) / 256, 256>>>(n);
    k_hist<<<(e + 255) / 256, 256>>>(ei, e);
    k_scan1<<<scan_blocks, SCAN_B>>>(n);
    k_scan2<<<1, 64>>>();
    k_scan3<<<scan_blocks, SCAN_B>>>(n, e);
    k_fill<<<(e + 255) / 256, 256>>>(ei, e);

    int agg_blocks = (n * 32 + 255) / 256;
    int xf_blocks = (n + XF_ROWS - 1) / XF_ROWS;

    // layer 1: agg(x) -> g_agg ; g_h = relu(g_agg@Wl1 + x@Wr1 + b1)
    k_agg<false><<<agg_blocks, 256>>>(x, n);
    k_xform<false, true, true><<<xf_blocks, 256>>>(x, Wl1, Wr1, b1, out, n);

    // layer 2: agg(g_h) -> g_agg ; out = g_agg@Wl2 + g_h@Wr2 + b2
    k_agg<true><<<agg_blocks, 256>>>(x, n);
    k_xform<true, false, false><<<xf_blocks, 256>>>(x, Wl2, Wr2, b2, out, n);
}

// round 10
// speedup vs baseline: 1.5102x; 1.0845x over previous
#include <cuda_runtime.h>
#include <cstdint>

#define NN 50000
#define NE 600000
#define DIM 128

#define SCAN_B 1024
#define NBLK ((NN + SCAN_B - 1) / SCAN_B)   // 49

// ---- device-global scratch (no runtime allocation allowed) ----
__device__ int   g_mode;          // 1 = edge_index is int64, 0 = int32
__device__ int   g_deg[NN];
__device__ int   g_off[NN + 1];
__device__ int   g_cur[NN];
__device__ float g_inv[NN];
__device__ int   g_blk[NBLK];
__device__ int   g_csr[NE];
__device__ float g_agg[(size_t)NN * DIM];
__device__ float g_h[(size_t)NN * DIM];

// ---------------- packed f32x2 helpers ----------------

__device__ __forceinline__ unsigned long long dup2(float v) {
    unsigned long long o;
    unsigned u = __float_as_uint(v);
    asm("mov.b64 %0, {%1, %1};" : "=l"(o) : "r"(u));
    return o;
}

#define FMA2(acc, a, b) \
    asm("fma.rn.f32x2 %0, %1, %2, %0;" : "+l"(acc) : "l"(a), "l"(b))

__device__ __forceinline__ float lo32(unsigned long long v) {
    return __uint_as_float((unsigned)(v & 0xffffffffull));
}
__device__ __forceinline__ float hi32(unsigned long long v) {
    return __uint_as_float((unsigned)(v >> 32));
}

// ---------------- edge-index dtype probe + decode ----------------

__global__ void k_probe(const void* __restrict__ ei, int n, int e) {
    if (threadIdx.x != 0 || blockIdx.x != 0) return;
    const long long* p = (const long long*)ei;
    int cnt = min(16, e);
    int ok = 1;
    for (int i = 0; i < cnt; i++) {
        long long v = p[i];
        if (v < 0 || v >= (long long)n) { ok = 0; break; }
    }
    g_mode = ok;
}

__device__ __forceinline__ int edge_at(const void* __restrict__ ei, int e,
                                       int which, int i, int mode) {
    if (mode) return (int)((const long long*)ei)[(size_t)which * e + i];
    return ((const int*)ei)[(size_t)which * e + i];
}

// ---------------- CSR build ----------------

__global__ void k_zero_deg(int n) {
    int i = blockIdx.x * blockDim.x + threadIdx.x;
    if (i < n) g_deg[i] = 0;
}

__global__ void k_hist(const void* __restrict__ ei, int e) {
    int i = blockIdx.x * blockDim.x + threadIdx.x;
    if (i < e) {
        int mode = g_mode;
        atomicAdd(&g_deg[edge_at(ei, e, 1, i, mode)], 1);
    }
}

__global__ void k_scan1(int n) {
    __shared__ int sm[SCAN_B];
    int t = threadIdx.x;
    int i = blockIdx.x * SCAN_B + t;
    int v = (i < n) ? g_deg[i] : 0;
    sm[t] = v;
    __syncthreads();
#pragma unroll
    for (int d = 1; d < SCAN_B; d <<= 1) {
        int u = (t >= d) ? sm[t - d] : 0;
        __syncthreads();
        sm[t] += u;
        __syncthreads();
    }
    if (i < n) g_off[i] = sm[t];
    if (t == SCAN_B - 1) g_blk[blockIdx.x] = sm[t];
}

__global__ void k_scan2() {
    __shared__ int sm[64];
    int t = threadIdx.x;
    int v = (t < NBLK) ? g_blk[t] : 0;
    sm[t] = v;
    __syncthreads();
#pragma unroll
    for (int d = 1; d < 64; d <<= 1) {
        int u = (t >= d) ? sm[t - d] : 0;
        __syncthreads();
        sm[t] += u;
        __syncthreads();
    }
    if (t < NBLK) g_blk[t] = sm[t] - v;
}

__global__ void k_scan3(int n, int e) {
    int t = threadIdx.x;
    int i = blockIdx.x * SCAN_B + t;
    if (i < n) {
        int dg = g_deg[i];
        int excl = g_blk[blockIdx.x] + g_off[i] - dg;
        g_off[i] = excl;
        g_cur[i] = excl;
        g_inv[i] = 1.0f / (float)max(dg, 1);
    }
    if (i == 0) g_off[n] = e;
}

__global__ void k_fill(const void* __restrict__ ei, int e) {
    int i = blockIdx.x * blockDim.x + threadIdx.x;
    if (i < e) {
        int mode = g_mode;
        int d = edge_at(ei, e, 1, i, mode);
        int s = edge_at(ei, e, 0, i, mode);
        int p = atomicAdd(&g_cur[d], 1);
        g_csr[p] = s;
    }
}

// ---------------- mean aggregation: one warp per node ----------------

template <bool FROM_H>
__global__ void k_agg(const float* __restrict__ xin, int n) {
    int w = (blockIdx.x * blockDim.x + threadIdx.x) >> 5;
    int lane = threadIdx.x & 31;
    if (w >= n) return;
    const float* feat = FROM_H ? (const float*)g_h : xin;
    int beg = g_off[w];
    int end = g_off[w + 1];
    const float4* fp = (const float4*)feat;
    float4 s = make_float4(0.f, 0.f, 0.f, 0.f);
#pragma unroll 4
    for (int e = beg; e < end; ++e) {
        int j = __ldg(&g_csr[e]);
        float4 v = __ldg(&fp[(size_t)j * 32 + lane]);
        s.x += v.x; s.y += v.y; s.z += v.z; s.w += v.w;
    }
    float iv = g_inv[w];
    ((float4*)g_agg)[(size_t)w * 32 + lane] =
        make_float4(s.x * iv, s.y * iv, s.z * iv, s.w * iv);
}

// ---------------- fused transform via packed f32x2 FMA ----------------
// out[128-row tile, 128] = A@Wl + X@Wr + b (optional relu)
// 256 threads. Warp w owns rows w*16..w*16+15 (8 row-pairs); lane colg owns
// cols 4*colg..+3. acc[rp][c] = {out[r0][c], out[r1][c]} packed f32x2.
// A_t/X_t stored K-MAJOR ([k][row]) so row-pair operand is one 8B broadcast LDS.

#define XF_ROWS 128
#define KCH 16

template <bool X_FROM_H, bool OUT_TO_H, bool RELU>
__global__ void __launch_bounds__(256, 2)
k_xform(const float* __restrict__ Xin,
        const float* __restrict__ Wl, const float* __restrict__ Wr,
        const float* __restrict__ bias, float* __restrict__ outp, int n) {
    __shared__ float Wl_t[KCH * 128];        // 8 KB, [k][col]
    __shared__ float Wr_t[KCH * 128];        // 8 KB
    __shared__ float A_t[KCH * XF_ROWS];     // 8 KB, [k][row]
    __shared__ float X_t[KCH * XF_ROWS];     // 8 KB

    const float* A = g_agg;
    const float* X = X_FROM_H ? (const float*)g_h : Xin;
    float* out = OUT_TO_H ? (float*)g_h : outp;

    int tx = threadIdx.x;
    int colg = tx & 31;
    int wrp = tx >> 5;            // warp 0..7 -> rows wrp*16..wrp*16+15
    int row0 = blockIdx.x * XF_ROWS;

    unsigned long long acc[8][4];
#pragma unroll
    for (int rp = 0; rp < 8; rp++)
#pragma unroll
        for (int c = 0; c < 4; c++) acc[rp][c] = 0ull;

    for (int kc = 0; kc < 128 / KCH; kc++) {
        __syncthreads();
        // weights chunk: k rows kc*16..+15, [k][col] layout; 512 float4 each
#pragma unroll
        for (int i = 0; i < 2; i++) {
            int idx = tx + i * 256;          // 0..511
            int r = idx >> 5;                // k row 0..15
            int c4 = idx & 31;
            ((float4*)Wl_t)[idx] = __ldg(&((const float4*)Wl)[(kc * KCH + r) * 32 + c4]);
            ((float4*)Wr_t)[idx] = __ldg(&((const float4*)Wr)[(kc * KCH + r) * 32 + c4]);
        }
        // A/X chunk -> K-MAJOR transpose in smem: 128 rows x 4 float4 (16 k)
#pragma unroll
        for (int i = 0; i < 2; i++) {
            int idx = tx + i * 256;          // 0..511
            int row = idx & 127;
            int kq = idx >> 7;               // float4 index within chunk 0..3
            int grow = row0 + row;
            float4 av = make_float4(0.f, 0.f, 0.f, 0.f);
            float4 xv = av;
            if (grow < n) {
                av = __ldg(&((const float4*)A)[(size_t)grow * 32 + kc * 4 + kq]);
                xv = __ldg(&((const float4*)X)[(size_t)grow * 32 + kc * 4 + kq]);
            }
            A_t[(kq * 4 + 0) * XF_ROWS + row] = av.x;
            A_t[(kq * 4 + 1) * XF_ROWS + row] = av.y;
            A_t[(kq * 4 + 2) * XF_ROWS + row] = av.z;
            A_t[(kq * 4 + 3) * XF_ROWS + row] = av.w;
            X_t[(kq * 4 + 0) * XF_ROWS + row] = xv.x;
            X_t[(kq * 4 + 1) * XF_ROWS + row] = xv.y;
            X_t[(kq * 4 + 2) * XF_ROWS + row] = xv.z;
            X_t[(kq * 4 + 3) * XF_ROWS + row] = xv.w;
        }
        __syncthreads();

#pragma unroll
        for (int k = 0; k < KCH; k++) {
            float4 lw = ((float4*)Wl_t)[k * 32 + colg];
            float4 rw = ((float4*)Wr_t)[k * 32 + colg];
            unsigned long long wl0 = dup2(lw.x), wl1 = dup2(lw.y),
                               wl2 = dup2(lw.z), wl3 = dup2(lw.w);
            unsigned long long wr0 = dup2(rw.x), wr1 = dup2(rw.y),
                               wr2 = dup2(rw.z), wr3 = dup2(rw.w);
            const float* Ak = A_t + k * XF_ROWS + wrp * 16;
            const float* Xk = X_t + k * XF_ROWS + wrp * 16;
#pragma unroll
            for (int rp = 0; rp < 8; rp++) {
                unsigned long long a2 = *(const unsigned long long*)(Ak + rp * 2);
                unsigned long long x2 = *(const unsigned long long*)(Xk + rp * 2);
                FMA2(acc[rp][0], a2, wl0);
                FMA2(acc[rp][1], a2, wl1);
                FMA2(acc[rp][2], a2, wl2);
                FMA2(acc[rp][3], a2, wl3);
                FMA2(acc[rp][0], x2, wr0);
                FMA2(acc[rp][1], x2, wr1);
                FMA2(acc[rp][2], x2, wr2);
                FMA2(acc[rp][3], x2, wr3);
            }
        }
    }

    float4 bv = __ldg(&((const float4*)bias)[colg]);
#pragma unroll
    for (int rp = 0; rp < 8; rp++) {
        int r0 = row0 + wrp * 16 + rp * 2;
#pragma unroll
        for (int half = 0; half < 2; half++) {
            int row = r0 + half;
            if (row < n) {
                float4 o;
                o.x = (half ? hi32(acc[rp][0]) : lo32(acc[rp][0])) + bv.x;
                o.y = (half ? hi32(acc[rp][1]) : lo32(acc[rp][1])) + bv.y;
                o.z = (half ? hi32(acc[rp][2]) : lo32(acc[rp][2])) + bv.z;
                o.w = (half ? hi32(acc[rp][3]) : lo32(acc[rp][3])) + bv.w;
                if (RELU) {
                    o.x = fmaxf(o.x, 0.f); o.y = fmaxf(o.y, 0.f);
                    o.z = fmaxf(o.z, 0.f); o.w = fmaxf(o.w, 0.f);
                }
                ((float4*)out)[(size_t)row * 32 + colg] = o;
            }
        }
    }
}

// ---------------- launch: kernel launches ONLY ----------------

extern "C" void kernel_launch(void* const* d_in, const int* in_sizes, int n_in,
                              void* d_out, int out_size) {
    const float* x   = (const float*)d_in[0];
    const void*  ei  = d_in[1];
    const float* Wl1 = (const float*)d_in[2];
    const float* Wr1 = (const float*)d_in[3];
    const float* b1  = (const float*)d_in[4];
    const float* Wl2 = (const float*)d_in[5];
    const float* Wr2 = (const float*)d_in[6];
    const float* b2  = (const float*)d_in[7];
    float*       out = (float*)d_out;

    int n = in_sizes[0] / DIM;
    int e = in_sizes[1] / 2;

    int scan_blocks = (n + SCAN_B - 1) / SCAN_B;

    // detect edge_index dtype (int32 vs int64), then build CSR
    k_probe<<<1, 32>>>(ei, n, e);
    k_zero_deg<<<(n + 255) / 256, 256>>>(n);
    k_hist<<<(e + 255) / 256, 256>>>(ei, e);
    k_scan1<<<scan_blocks, SCAN_B>>>(n);
    k_scan2<<<1, 64>>>();
    k_scan3<<<scan_blocks, SCAN_B>>>(n, e);
    k_fill<<<(e + 255) / 256, 256>>>(ei, e);

    int agg_blocks = (n * 32 + 255) / 256;
    int xf_blocks = (n + XF_ROWS - 1) / XF_ROWS;

    // layer 1: agg(x) -> g_agg ; g_h = relu(g_agg@Wl1 + x@Wr1 + b1)
    k_agg<false><<<agg_blocks, 256>>>(x, n);
    k_xform<false, true, true><<<xf_blocks, 256>>>(x, Wl1, Wr1, b1, out, n);

    // layer 2: agg(g_h) -> g_agg ; out = g_agg@Wl2 + g_h@Wr2 + b2
    k_agg<true><<<agg_blocks, 256>>>(x, n);
    k_xform<true, false, false><<<xf_blocks, 256>>>(x, Wl2, Wr2, b2, out, n);
}